// round 1
// baseline (speedup 1.0000x reference)
#include <cuda_runtime.h>

// UnionLayer: out[b, 0:256]   = -1/(-1 + sum_d log(1 - (1-x[b,d]) * W_con[n,d]))
//             out[b, 256:512] = 1 - ( -1/(-1 + sum_d log(1 - x[b,d] * W_dis[n,d])) )
// B=1024, D=512, N=256. Strategy: log(prod) trick — multiply runs of 64 terms
// (each term in (0.5, 1], so prod >= 0.5^64 ~ 5e-20, safe in fp32), log once.
// GEMM-style tiling: 64x64 CTA tile, 4x4 register tile, BK=32 double-buffered.

#define BM 64
#define BN 64
#define BK 32
#define PAD 33          // smem row pad (floats): X reads broadcast, W reads 2-way
#define DDIM 512
#define NOUT 512        // 2N
#define NCOLS 256       // N

__global__ __launch_bounds__(256) void union_kernel(
    const float* __restrict__ x,
    const float* __restrict__ Wcon,
    const float* __restrict__ Wdis,
    float* __restrict__ out)
{
    __shared__ float Xs[2][BM * PAD];
    __shared__ float Ws[2][BN * PAD];

    const int tid = threadIdx.x;
    const int tx = tid & 15;        // N direction (4 cols each)
    const int ty = tid >> 4;        // M direction (4 rows each)
    const int bn0 = blockIdx.x * BN;
    const int bm0 = blockIdx.y * BM;
    const int z   = blockIdx.z;     // 0 = con, 1 = dis
    const float* __restrict__ W = z ? Wdis : Wcon;

    float acc[16], prod[16];
#pragma unroll
    for (int i = 0; i < 16; i++) { acc[i] = 0.0f; prod[i] = 1.0f; }

    float4 xv[2], wv[2];

    // ---- load chunk 0 ----
#pragma unroll
    for (int i = 0; i < 2; i++) {
        int f = tid + 256 * i;
        int r = f >> 3;
        int c = (f & 7) << 2;
        xv[i] = *reinterpret_cast<const float4*>(&x[(bm0 + r) * DDIM + c]);
        wv[i] = *reinterpret_cast<const float4*>(&W[(bn0 + r) * DDIM + c]);
    }
#pragma unroll
    for (int i = 0; i < 2; i++) {
        int f = tid + 256 * i;
        int r = f >> 3;
        int c = (f & 7) << 2;
        float4 v = xv[i];
        if (z == 0) { v.x = 1.0f - v.x; v.y = 1.0f - v.y; v.z = 1.0f - v.z; v.w = 1.0f - v.w; }
        Xs[0][r * PAD + c + 0] = v.x;
        Xs[0][r * PAD + c + 1] = v.y;
        Xs[0][r * PAD + c + 2] = v.z;
        Xs[0][r * PAD + c + 3] = v.w;
        float4 w4 = wv[i];
        Ws[0][r * PAD + c + 0] = w4.x;
        Ws[0][r * PAD + c + 1] = w4.y;
        Ws[0][r * PAD + c + 2] = w4.z;
        Ws[0][r * PAD + c + 3] = w4.w;
    }
    __syncthreads();

    const int NCHUNK = DDIM / BK;   // 16

    for (int ck = 0; ck < NCHUNK; ck++) {
        const int buf = ck & 1;

        // prefetch next chunk (global -> regs), overlapped with compute
        if (ck + 1 < NCHUNK) {
            int d0 = (ck + 1) * BK;
#pragma unroll
            for (int i = 0; i < 2; i++) {
                int f = tid + 256 * i;
                int r = f >> 3;
                int c = (f & 7) << 2;
                xv[i] = *reinterpret_cast<const float4*>(&x[(bm0 + r) * DDIM + d0 + c]);
                wv[i] = *reinterpret_cast<const float4*>(&W[(bn0 + r) * DDIM + d0 + c]);
            }
        }

        // ---- compute on buf ----
        const float* __restrict__ Xp = Xs[buf];
        const float* __restrict__ Wp = Ws[buf];
#pragma unroll
        for (int k = 0; k < BK; k++) {
            float a0 = Xp[(ty * 4 + 0) * PAD + k];
            float a1 = Xp[(ty * 4 + 1) * PAD + k];
            float a2 = Xp[(ty * 4 + 2) * PAD + k];
            float a3 = Xp[(ty * 4 + 3) * PAD + k];
            float b0 = Wp[(tx * 4 + 0) * PAD + k];
            float b1 = Wp[(tx * 4 + 1) * PAD + k];
            float b2 = Wp[(tx * 4 + 2) * PAD + k];
            float b3 = Wp[(tx * 4 + 3) * PAD + k];
            prod[ 0] *= fmaf(-a0, b0, 1.0f);
            prod[ 1] *= fmaf(-a0, b1, 1.0f);
            prod[ 2] *= fmaf(-a0, b2, 1.0f);
            prod[ 3] *= fmaf(-a0, b3, 1.0f);
            prod[ 4] *= fmaf(-a1, b0, 1.0f);
            prod[ 5] *= fmaf(-a1, b1, 1.0f);
            prod[ 6] *= fmaf(-a1, b2, 1.0f);
            prod[ 7] *= fmaf(-a1, b3, 1.0f);
            prod[ 8] *= fmaf(-a2, b0, 1.0f);
            prod[ 9] *= fmaf(-a2, b1, 1.0f);
            prod[10] *= fmaf(-a2, b2, 1.0f);
            prod[11] *= fmaf(-a2, b3, 1.0f);
            prod[12] *= fmaf(-a3, b0, 1.0f);
            prod[13] *= fmaf(-a3, b1, 1.0f);
            prod[14] *= fmaf(-a3, b2, 1.0f);
            prod[15] *= fmaf(-a3, b3, 1.0f);
        }

        // store next chunk to other buffer
        if (ck + 1 < NCHUNK) {
            const int nb = buf ^ 1;
#pragma unroll
            for (int i = 0; i < 2; i++) {
                int f = tid + 256 * i;
                int r = f >> 3;
                int c = (f & 7) << 2;
                float4 v = xv[i];
                if (z == 0) { v.x = 1.0f - v.x; v.y = 1.0f - v.y; v.z = 1.0f - v.z; v.w = 1.0f - v.w; }
                Xs[nb][r * PAD + c + 0] = v.x;
                Xs[nb][r * PAD + c + 1] = v.y;
                Xs[nb][r * PAD + c + 2] = v.z;
                Xs[nb][r * PAD + c + 3] = v.w;
                float4 w4 = wv[i];
                Ws[nb][r * PAD + c + 0] = w4.x;
                Ws[nb][r * PAD + c + 1] = w4.y;
                Ws[nb][r * PAD + c + 2] = w4.z;
                Ws[nb][r * PAD + c + 3] = w4.w;
            }
        }

        // flush products to log-sum every 2 chunks (64 terms, prod >= 0.5^64)
        if (ck & 1) {
#pragma unroll
            for (int i = 0; i < 16; i++) {
                acc[i] += __logf(prod[i]);
                prod[i] = 1.0f;
            }
        }

        __syncthreads();
    }

    // ---- epilogue: y = -1/(-1+acc) = 1/(1-acc); dis: 1 - y ----
#pragma unroll
    for (int i = 0; i < 4; i++) {
        int row = bm0 + ty * 4 + i;
        float4 o;
        float v0 = 1.0f / (1.0f - acc[i * 4 + 0]);
        float v1 = 1.0f / (1.0f - acc[i * 4 + 1]);
        float v2 = 1.0f / (1.0f - acc[i * 4 + 2]);
        float v3 = 1.0f / (1.0f - acc[i * 4 + 3]);
        if (z) { v0 = 1.0f - v0; v1 = 1.0f - v1; v2 = 1.0f - v2; v3 = 1.0f - v3; }
        o.x = v0; o.y = v1; o.z = v2; o.w = v3;
        *reinterpret_cast<float4*>(&out[row * NOUT + z * NCOLS + bn0 + tx * 4]) = o;
    }
}

extern "C" void kernel_launch(void* const* d_in, const int* in_sizes, int n_in,
                              void* d_out, int out_size)
{
    const float* x    = (const float*)d_in[0];
    const float* Wcon = (const float*)d_in[1];
    const float* Wdis = (const float*)d_in[2];
    float* out = (float*)d_out;

    dim3 grid(NCOLS / BN, 1024 / BM, 2);   // (4, 16, 2) = 128 CTAs
    union_kernel<<<grid, 256>>>(x, Wcon, Wdis, out);
}